// round 15
// baseline (speedup 1.0000x reference)
#include <cuda_runtime.h>
#include <math.h>

#define Bb 4
#define Nn 2047
#define N1 2048
#define Ii 256
#define Oo 128
#define Hh 4
#define SLOPEF 0.2f
#define NBH (Bb * Hh)
#define SEGS 64
#define SEGLEN 32
#define SEGSH 5
#define NP1 2049

typedef unsigned long long ull;

// ---------------- scratch (device globals) ----------------
__device__ float g_hph[Bb * Hh * N1 * Oo];      // 16 MB
__device__ float g_ssrc[NBH * N1];
__device__ float g_sdst[NBH * N1];
__device__ float g_Ei[NBH * N1], g_Fi[NBH * N1];
__device__ unsigned char g_runi[NBH * N1];
__device__ float g_part[Bb * 128 * Oo];         // per-tile column sums of hp
__device__ float g_meanhp[NBH * Oo];
__device__ ull   g_comps[NBH * N1];             // per-chunk sorted composites
__device__ float g_cmax[NBH * 8];               // per-chunk unmasked max of s_dst
__device__ float g_skey[NBH * N1];
__device__ int   g_sidx[NBH * N1];
__device__ float g_wE[NBH * N1], g_wF[NBH * N1];
__device__ float g_SE[(size_t)NBH * NP1 * Oo];
__device__ float g_PF[(size_t)NBH * NP1 * Oo];
__device__ float g_sSE[NBH * NP1], g_sPF[NBH * NP1];
__device__ float g_offE[NBH * SEGS * Oo], g_offF[NBH * SEGS * Oo];
__device__ int   g_ti[NBH * N1];
__device__ float g_invl[NBH * N1];
__device__ int   g_mask_is_int;                 // written identically by every ksort1 block

__device__ __forceinline__ float fast_tanh(float x) {
    float cx = fminf(fmaxf(x, -15.f), 15.f);
    float e = __expf(2.f * cx);
    return __fdividef(e - 1.f, e + 1.f);
}

__device__ __forceinline__ ull packf2(float v) {
    ull r;
    asm("mov.b64 %0, {%1, %1};" : "=l"(r) : "f"(v));
    return r;
}
__device__ __forceinline__ void fma2(ull& d, ull a, ull b) {
    asm("fma.rn.f32x2 %0, %1, %2, %0;" : "+l"(d) : "l"(a), "l"(b));
}
__device__ __forceinline__ void unpackf2(ull v, float& lo, float& hi) {
    asm("mov.b64 {%0, %1}, %2;" : "=f"(lo), "=f"(hi) : "l"(v));
}
// monotone float -> uint32 mapping for sorting (bit-exact invertible)
__device__ __forceinline__ unsigned f2sort(float f) {
    unsigned u = __float_as_uint(f);
    return u ^ ((unsigned)((int)u >> 31) | 0x80000000u);
}
__device__ __forceinline__ float sort2f(unsigned s) {
    unsigned u = (s & 0x80000000u) ? (s ^ 0x80000000u) : ~s;
    return __uint_as_float(u);
}

// ---------------- K12: fused self_linear + head projection + scores, double-buffered ------
__global__ __launch_bounds__(256) void k12_fused(const float* __restrict__ x,
                                                 const float* __restrict__ prior,
                                                 const float* __restrict__ Wlin,
                                                 const float* __restrict__ whead,
                                                 const float* __restrict__ asrc,
                                                 const float* __restrict__ adst) {
    __shared__ float xs[2][32][33];
    __shared__ float ws2[2][32][130];
    __shared__ float hpt[32][130];

    const int ib = blockIdx.x;
    const int nb = ib * 32;
    const int b = blockIdx.y;
    const int t = threadIdx.x;
    const int tr = t >> 4;
    const int tc = t & 15;

    // ---- Phase A: hp tile (8 K-chunks, double-buffered) ----
    ull acc[2][4];
#pragma unroll
    for (int ar = 0; ar < 2; ++ar)
#pragma unroll
        for (int c = 0; c < 4; ++c) acc[ar][c] = 0ull;

#pragma unroll
    for (int it = 0; it < 4; ++it) {
        int idx = t + 256 * it;
        int r = idx >> 5, k = idx & 31;
        int gn = nb + r;
        xs[0][r][k] = (gn < Nn) ? x[(b * Nn + gn) * Ii + k] : 0.f;
    }
#pragma unroll
    for (int it = 0; it < 16; ++it) {
        int idx = t + 256 * it;
        int p = idx >> 5, k = idx & 31;
        ws2[0][k][p] = Wlin[p * Ii + k];
    }
    __syncthreads();

    for (int kbi = 0; kbi < 8; ++kbi) {
        const int cur = kbi & 1;
        if (kbi < 7) {
            const int kb = (kbi + 1) * 32;
            const int nxt = 1 - cur;
#pragma unroll
            for (int it = 0; it < 4; ++it) {
                int idx = t + 256 * it;
                int r = idx >> 5, k = idx & 31;
                int gn = nb + r;
                xs[nxt][r][k] = (gn < Nn) ? x[(b * Nn + gn) * Ii + kb + k] : 0.f;
            }
#pragma unroll
            for (int it = 0; it < 16; ++it) {
                int idx = t + 256 * it;
                int p = idx >> 5, k = idx & 31;
                ws2[nxt][k][p] = Wlin[p * Ii + kb + k];
            }
        }
#pragma unroll
        for (int k = 0; k < 32; ++k) {
            ull pp0 = packf2(xs[cur][tr][k]);
            ull pp1 = packf2(xs[cur][tr + 16][k]);
#pragma unroll
            for (int c = 0; c < 4; ++c) {
                ull wv = *(const ull*)&ws2[cur][k][2 * tc + 32 * c];
                fma2(acc[0][c], pp0, wv);
                fma2(acc[1][c], pp1, wv);
            }
        }
        __syncthreads();
    }

#pragma unroll
    for (int ar = 0; ar < 2; ++ar) {
        int r = tr + 16 * ar;
        int gn = nb + r;
        bool isprior = (gn == Nn);
#pragma unroll
        for (int c = 0; c < 4; ++c) {
            int col = 2 * tc + 32 * c;
            float lo, hi;
            unpackf2(acc[ar][c], lo, hi);
            if (isprior) { lo = prior[b * Oo + col]; hi = prior[b * Oo + col + 1]; }
            hpt[r][col] = lo;
            hpt[r][col + 1] = hi;
        }
    }
    __syncthreads();
    {
        int col = t & 127;
        int half = t >> 7;
        float s = 0.f;
#pragma unroll
        for (int r = half * 16; r < half * 16 + 16; ++r) s += hpt[r][col];
        g_part[((b * 64 + ib) * 2 + half) * Oo + col] = s;
    }

    // ---- Phase B: 16 chunks (4 heads x 4 K-chunks), double-buffered ----
#pragma unroll
    for (int it = 0; it < 16; ++it) {
        int idx = t + 256 * it;
        int o = idx >> 7, p = idx & 127;
        ws2[0][o][p] = whead[(size_t)o * Oo + p];
    }
    ull a2[2][4];
#pragma unroll
    for (int ar = 0; ar < 2; ++ar)
#pragma unroll
        for (int c = 0; c < 4; ++c) a2[ar][c] = 0ull;
    __syncthreads();

    for (int ci = 0; ci < 16; ++ci) {
        const int cur = ci & 1;
        if (ci < 15) {
            const int nh = (ci + 1) >> 2;
            const int nkb = ((ci + 1) & 3) * 32;
            const int nxt = 1 - cur;
#pragma unroll
            for (int it = 0; it < 16; ++it) {
                int idx = t + 256 * it;
                int o = idx >> 7, p = idx & 127;
                ws2[nxt][o][p] = whead[(size_t)(nh * Oo + nkb + o) * Oo + p];
            }
        }
        const int kb = (ci & 3) * 32;
#pragma unroll
        for (int k = 0; k < 32; ++k) {
            ull pp0 = packf2(hpt[tr][kb + k]);
            ull pp1 = packf2(hpt[tr + 16][kb + k]);
#pragma unroll
            for (int c = 0; c < 4; ++c) {
                ull wv = *(const ull*)&ws2[cur][k][2 * tc + 32 * c];
                fma2(a2[0][c], pp0, wv);
                fma2(a2[1][c], pp1, wv);
            }
        }
        if ((ci & 3) == 3) {
            const int h = ci >> 2;
            const int bh = b * Hh + h;
#pragma unroll
            for (int ar = 0; ar < 2; ++ar) {
                int r = tr + 16 * ar;
                int gn = nb + r;
                float ps = 0.f, pd = 0.f;
#pragma unroll
                for (int c = 0; c < 4; ++c) {
                    int col = 2 * tc + 32 * c;
                    float lo, hi;
                    unpackf2(a2[ar][c], lo, hi);
                    *(float2*)&g_hph[((size_t)bh * N1 + gn) * Oo + col] = make_float2(lo, hi);
                    float t0 = fast_tanh(lo);
                    float t1 = fast_tanh(hi);
                    ps = fmaf(t0, asrc[h * Oo + col], fmaf(t1, asrc[h * Oo + col + 1], ps));
                    pd = fmaf(t0, adst[h * Oo + col], fmaf(t1, adst[h * Oo + col + 1], pd));
                }
#pragma unroll
                for (int off = 8; off; off >>= 1) {
                    ps += __shfl_xor_sync(0xffffffffu, ps, off);
                    pd += __shfl_xor_sync(0xffffffffu, pd, off);
                }
                if (tc == 0) {
                    g_ssrc[bh * N1 + gn] = ps;
                    g_sdst[bh * N1 + gn] = pd;
                }
            }
#pragma unroll
            for (int ar = 0; ar < 2; ++ar)
#pragma unroll
                for (int c = 0; c < 4; ++c) a2[ar][c] = 0ull;
        }
        __syncthreads();
    }
}

// ---------------- KSort1: mask detect + chunk max + chunk sort (composite w/ dead bit) ----
// composite = key<<16 | dead<<15 | n   (n in [0,2048) fits 11 bits)
__global__ __launch_bounds__(256) void ksort1(const void* __restrict__ xmask) {
    __shared__ ull ch[256];
    __shared__ float red8[8];
    __shared__ int sbyteflag;
    const int c = blockIdx.x;    // chunk 0..7
    const int bh = blockIdx.y;
    const int b = bh / Hh;
    const int t = threadIdx.x;

    if (t == 0) sbyteflag = 0;
    __syncthreads();
    {
        const unsigned* mw = (const unsigned*)xmask;
        bool loc = false;
#pragma unroll
        for (int n = t; n < 2048; n += 256)   // 8192 bytes, safe for both layouts
            if (mw[n] > 1u) loc = true;
        if (loc) sbyteflag = 1;   // benign same-value race
    }
    __syncthreads();
    const bool mii = (sbyteflag == 0);

    const int n = c * 256 + t;
    float sd = g_sdst[bh * N1 + n];
    bool mj = mii ? (((const int*)xmask)[b * N1 + n] != 0)
                  : (((const unsigned char*)xmask)[b * N1 + n] != 0);

    // chunk max over unmasked
    float v = mj ? -INFINITY : sd;
#pragma unroll
    for (int off = 16; off; off >>= 1) v = fmaxf(v, __shfl_xor_sync(0xffffffffu, v, off));
    if ((t & 31) == 0) red8[t >> 5] = v;
    __syncthreads();
    if (t == 0) {
        float m = red8[0];
#pragma unroll
        for (int i = 1; i < 8; ++i) m = fmaxf(m, red8[i]);
        g_cmax[bh * 8 + c] = m;
        g_mask_is_int = mii ? 1 : 0;   // every block writes the same value
    }

    ch[t] = ((ull)f2sort(sd) << 16) | (mj ? 0x8000ull : 0ull) | (unsigned)n;
    __syncthreads();
    for (int k = 2; k <= 256; k <<= 1) {
        for (int j = k >> 1; j > 0; j >>= 1) {
            int ixj = t ^ j;
            if (ixj > t) {
                bool up = ((t & k) == 0);
                ull ci = ch[t], cj = ch[ixj];
                if (up ? (ci > cj) : (ci < cj)) {
                    ch[t] = cj;
                    ch[ixj] = ci;
                }
            }
            __syncthreads();
        }
    }
    g_comps[bh * N1 + n] = ch[t];
}

// ---------------- KMerge: wide merge-by-rank + factors + (block 0) meanhp ----------------
// 512 threads, grid (4, NBH): block x handles natural/sorted slots [x*512, x*512+512).
__global__ __launch_bounds__(512) void kmerge(const void* __restrict__ xmask,
                                              const float* __restrict__ whead) {
    __shared__ ull comps[N1];      // 16 KB (8 sorted chunks of 256)
    __shared__ float m0[Oo];
    const int blk = blockIdx.x;    // 0..3
    const int bh = blockIdx.y;
    const int b = bh / Hh;
    const int h = bh - b * Hh;
    const int t = threadIdx.x;

    for (int i = t; i < N1; i += 512) comps[i] = g_comps[bh * N1 + i];

    // Mdst from per-chunk maxima
    float Mdst = -INFINITY;
#pragma unroll
    for (int i = 0; i < 8; ++i) Mdst = fmaxf(Mdst, g_cmax[bh * 8 + i]);
    const bool nou = (Mdst == -INFINITY);
    const bool mii = (g_mask_is_int != 0);

    // natural-order factors: Ei/Fi/runi (this block's 512 natural indices)
    {
        int n = blk * 512 + t;
        int gidx = bh * N1 + n;
        float si = g_ssrc[gidx];
        bool mj = mii ? (((const int*)xmask)[b * N1 + n] != 0)
                      : (((const unsigned char*)xmask)[b * N1 + n] != 0);
        bool dead = nou || mj;
        float xm = si + Mdst;
        float m = (xm >= 0.f) ? xm : SLOPEF * xm;
        g_Ei[gidx] = dead ? 0.f : __expf(xm - m);
        g_Fi[gidx] = dead ? 0.f : __expf(SLOPEF * xm - m);
        g_runi[gidx] = dead ? 1 : 0;
    }

    // block 0: meanhp part 1 — m0 = mean over n of hp (reduce g_part)
    if (blk == 0 && t < Oo) {
        float s = 0.f;
#pragma unroll 4
        for (int p = 0; p < 128; ++p) s += g_part[(b * 128 + p) * Oo + t];
        m0[t] = s * (1.f / (float)N1);
    }
    __syncthreads();

    // merge-by-rank (exact: composites unique) + sorted-order outputs
    {
        int slot = blk * 512 + t;
        ull e = comps[slot];
        int rank = slot & 255;       // local position within own sorted chunk
        int cown = slot >> 8;
#pragma unroll
        for (int c2 = 0; c2 < 8; ++c2) {
            if (c2 == cown) continue;
            const int base = c2 << 8;
            int lo = 0, hi = 256;
#pragma unroll
            for (int it = 0; it < 9; ++it) {
                if (lo < hi) {
                    int mid = (lo + hi) >> 1;
                    if (comps[base + mid] < e) lo = mid + 1; else hi = mid;
                }
            }
            rank += lo;
        }
        int j = (int)(e & 0x7FFu);
        float key = sort2f((unsigned)(e >> 16));   // bit-exact s_dst[j]
        bool deadj = nou || ((e >> 15) & 1ull);
        int o = bh * N1 + rank;
        g_skey[o] = key;
        g_sidx[o] = j;
        g_wE[o] = deadj ? 0.f : __expf(key - Mdst);
        g_wF[o] = deadj ? 0.f : __expf(SLOPEF * (key - Mdst));
    }

    // block 0: meanhp part 2 — dot with w_head
    if (blk == 0 && t < Oo) {
        float acc = 0.f;
#pragma unroll 8
        for (int o = 0; o < Oo; ++o) acc = fmaf(m0[o], whead[(h * Oo + o) * Oo + t], acc);
        g_meanhp[bh * Oo + t] = acc;
    }
}

// ---------------- KScan: segmented scans, 64 segments x 32 rows ----------------
__global__ __launch_bounds__(256) void kscan() {
    __shared__ float wE[SEGLEN], wF[SEGLEN];
    __shared__ int sidx[SEGLEN];
    const int s = blockIdx.x;
    const int bh = blockIdx.y;
    const int t = threadIdx.x;
    const int col = t & 127;
    const int job = t >> 7;

    if (t < SEGLEN) {
        int r = s * SEGLEN + t;
        wE[t] = g_wE[bh * N1 + r];
        wF[t] = g_wF[bh * N1 + r];
        sidx[t] = g_sidx[bh * N1 + r];
    }
    __syncthreads();

    const float* hph = g_hph + (size_t)bh * N1 * Oo;
    const size_t outbase = ((size_t)bh * NP1 + s * SEGLEN) * Oo;

    if (job == 0) {
        float acc = 0.f, sacc = 0.f;
#pragma unroll 8
        for (int r = 0; r < SEGLEN; ++r) {
            float v = hph[(size_t)sidx[r] * Oo + col];
            acc = fmaf(wF[r], v, acc);
            g_PF[outbase + (size_t)(r + 1) * Oo + col] = acc;
            if (col == 0) {
                sacc += wF[r];
                g_sPF[bh * NP1 + s * SEGLEN + r + 1] = sacc;
            }
        }
    } else {
        float acc = 0.f, sacc = 0.f;
#pragma unroll 8
        for (int r = SEGLEN - 1; r >= 0; --r) {
            float v = hph[(size_t)sidx[r] * Oo + col];
            acc = fmaf(wE[r], v, acc);
            g_SE[outbase + (size_t)r * Oo + col] = acc;
            if (col == 0) {
                sacc += wE[r];
                g_sSE[bh * NP1 + s * SEGLEN + r] = sacc;
            }
        }
    }
}

// ---------------- KTiOff: staged segment offsets + per-row threshold + 1/l ----------------
__global__ __launch_bounds__(1024) void ktioff() {
    __shared__ float keys[N1];                 // 8 KB
    __shared__ float bufE[SEGS][Oo];           // 32 KB segment-head SE rows
    __shared__ float bufF[SEGS][Oo];           // 32 KB segment-tail PF rows
    __shared__ float sheadE[SEGS], stailF[SEGS];
    __shared__ float ssoffE[SEGS + 1], ssoffF[SEGS + 1];
    const int bh = blockIdx.x;
    const int t = threadIdx.x;

    for (int i = t; i < SEGS * Oo; i += 1024) {
        int s = i >> 7, col = i & 127;
        bufE[s][col] = g_SE[((size_t)bh * NP1 + s * SEGLEN) * Oo + col];
        bufF[s][col] = g_PF[((size_t)bh * NP1 + s * SEGLEN + SEGLEN) * Oo + col];
    }
    if (t < SEGS) sheadE[t] = g_sSE[bh * NP1 + t * SEGLEN];
    else if (t < 2 * SEGS) stailF[t - SEGS] = g_sPF[bh * NP1 + (t - SEGS) * SEGLEN + SEGLEN];
    for (int i = t; i < N1; i += 1024) keys[i] = g_skey[bh * N1 + i];
    __syncthreads();

    if (t < 128) {
        float acc = 0.f;
        for (int s = SEGS - 1; s >= 0; --s) {
            g_offE[(bh * SEGS + s) * Oo + t] = acc;
            acc += bufE[s][t];
        }
        float accF = 0.f;
        for (int s = 0; s < SEGS; ++s) {
            g_offF[(bh * SEGS + s) * Oo + t] = accF;
            accF += bufF[s][t];
        }
    } else if (t == 128) {
        float a = 0.f;
        for (int s = SEGS - 1; s >= 0; --s) { ssoffE[s] = a; a += sheadE[s]; }
    } else if (t == 129) {
        float aF = 0.f;
        for (int s = 0; s < SEGS; ++s) { ssoffF[s] = aF; aF += stailF[s]; }
    }
    __syncthreads();

#pragma unroll
    for (int i = t; i < N1; i += 1024) {
        int idx = bh * N1 + i;
        float target = -g_ssrc[idx];
        int lo = 0, hi = N1;
#pragma unroll
        for (int it = 0; it < 12; ++it) {
            if (lo < hi) {
                int mid = (lo + hi) >> 1;
                if (keys[mid] >= target) hi = mid; else lo = mid + 1;
            }
        }
        int ti = lo;
        float Ei = g_Ei[idx], Fi = g_Fi[idx];
        float sse = (ti == N1) ? 0.f : g_sSE[bh * NP1 + ti] + ssoffE[ti >> SEGSH];
        float spf = (ti == 0) ? 0.f : g_sPF[bh * NP1 + ti] + ssoffF[(ti - 1) >> SEGSH];
        float li = Ei * sse + Fi * spf;
        g_ti[idx] = ti;
        g_invl[idx] = 1.f / li;
    }
}

// ---------------- KOut: gather + combine + head-mean + bias ----------------
__global__ __launch_bounds__(256) void kout(const float* __restrict__ bias,
                                            float* __restrict__ out) {
    __shared__ float mhs[Oo];
    __shared__ int tis[32];
    __shared__ float Eis[32], Fis[32], invl[32];
    __shared__ unsigned char runi[32];

    const int ib = blockIdx.x;
    const int b = blockIdx.y;
    const int t = threadIdx.x;
    const int col = t & 127;
    const int rh = t >> 7;

    float sum[16];
#pragma unroll
    for (int rr = 0; rr < 16; ++rr) sum[rr] = 0.f;

    for (int h = 0; h < Hh; ++h) {
        const int bh = b * Hh + h;
        __syncthreads();
        if (t < 32) {
            int idx = bh * N1 + ib * 32 + t;
            tis[t] = g_ti[idx];
            Eis[t] = g_Ei[idx];
            Fis[t] = g_Fi[idx];
            invl[t] = g_invl[idx];
            runi[t] = g_runi[idx];
        }
        if (t < Oo) mhs[t] = g_meanhp[bh * Oo + t];
        __syncthreads();

#pragma unroll 4
        for (int rr = 0; rr < 16; ++rr) {
            int r = rh + 2 * rr;
            if (runi[r]) { sum[rr] += mhs[col]; continue; }
            int ti = tis[r];
            float se = (ti == N1) ? 0.f
                : g_SE[((size_t)bh * NP1 + ti) * Oo + col] + g_offE[(bh * SEGS + (ti >> SEGSH)) * Oo + col];
            float pf = (ti == 0) ? 0.f
                : g_PF[((size_t)bh * NP1 + ti) * Oo + col] + g_offF[(bh * SEGS + ((ti - 1) >> SEGSH)) * Oo + col];
            sum[rr] += (Eis[r] * se + Fis[r] * pf) * invl[r];
        }
    }

    float* outp = out + ((size_t)b * N1 + ib * 32) * Oo;
#pragma unroll
    for (int rr = 0; rr < 16; ++rr) {
        int r = rh + 2 * rr;
        outp[r * Oo + col] = 0.25f * sum[rr] + bias[col];
    }
}

// ---------------- launch ----------------
extern "C" void kernel_launch(void* const* d_in, const int* in_sizes, int n_in,
                              void* d_out, int out_size) {
    const float* x = (const float*)d_in[0];
    const float* prior = (const float*)d_in[1];
    const void* xmask = d_in[2];
    const float* Wlin = (const float*)d_in[3];
    const float* whead = (const float*)d_in[4];
    const float* asrc = (const float*)d_in[5];
    const float* adst = (const float*)d_in[6];
    const float* bias = (const float*)d_in[7];
    float* out = (float*)d_out;

    k12_fused<<<dim3(64, Bb), 256>>>(x, prior, Wlin, whead, asrc, adst);
    ksort1<<<dim3(8, NBH), 256>>>(xmask);
    kmerge<<<dim3(4, NBH), 512>>>(xmask, whead);
    kscan<<<dim3(SEGS, NBH), 256>>>();
    ktioff<<<NBH, 1024>>>();
    kout<<<dim3(64, Bb), 256>>>(bias, out);
}

// round 16
// speedup vs baseline: 1.5372x; 1.5372x over previous
#include <cuda_runtime.h>
#include <math.h>

#define Bb 4
#define Nn 2047
#define N1 2048
#define Ii 256
#define Oo 128
#define Hh 4
#define SLOPEF 0.2f
#define NBH (Bb * Hh)
#define SEGS 64
#define SEGLEN 32
#define SEGSH 5
#define NP1 2049

typedef unsigned long long ull;

// ---------------- scratch (device globals) ----------------
__device__ float g_hph[Bb * Hh * N1 * Oo];      // 16 MB
__device__ float g_ssrc[NBH * N1];
__device__ float g_sdst[NBH * N1];
__device__ float g_Ei[NBH * N1], g_Fi[NBH * N1];
__device__ unsigned char g_runi[NBH * N1];
__device__ float g_part[Bb * 128 * Oo];         // per-tile column sums of hp
__device__ float g_meanhp[NBH * Oo];
__device__ ull   g_comps[NBH * N1];             // per-chunk sorted composites
__device__ float g_cmax[NBH * 8];               // per-chunk unmasked max of s_dst
__device__ float g_skey[NBH * N1];
__device__ int   g_sidx[NBH * N1];
__device__ float g_wE[NBH * N1], g_wF[NBH * N1];
__device__ float g_SE[(size_t)NBH * NP1 * Oo];
__device__ float g_PF[(size_t)NBH * NP1 * Oo];
__device__ float g_sSE[NBH * NP1], g_sPF[NBH * NP1];
__device__ float g_offE[NBH * SEGS * Oo], g_offF[NBH * SEGS * Oo];
__device__ int   g_ti[NBH * N1];
__device__ float g_invl[NBH * N1];
__device__ int   g_mask_is_int;                 // written identically by every ksort1 block

__device__ __forceinline__ float fast_tanh(float x) {
    float cx = fminf(fmaxf(x, -15.f), 15.f);
    float e = __expf(2.f * cx);
    return __fdividef(e - 1.f, e + 1.f);
}

__device__ __forceinline__ ull packf2(float v) {
    ull r;
    asm("mov.b64 %0, {%1, %1};" : "=l"(r) : "f"(v));
    return r;
}
__device__ __forceinline__ void fma2(ull& d, ull a, ull b) {
    asm("fma.rn.f32x2 %0, %1, %2, %0;" : "+l"(d) : "l"(a), "l"(b));
}
__device__ __forceinline__ void unpackf2(ull v, float& lo, float& hi) {
    asm("mov.b64 {%0, %1}, %2;" : "=f"(lo), "=f"(hi) : "l"(v));
}
// monotone float -> uint32 mapping for sorting (bit-exact invertible)
__device__ __forceinline__ unsigned f2sort(float f) {
    unsigned u = __float_as_uint(f);
    return u ^ ((unsigned)((int)u >> 31) | 0x80000000u);
}
__device__ __forceinline__ float sort2f(unsigned s) {
    unsigned u = (s & 0x80000000u) ? (s ^ 0x80000000u) : ~s;
    return __uint_as_float(u);
}

// ---------------- K12: fused self_linear + head projection + scores, double-buffered ------
__global__ __launch_bounds__(256) void k12_fused(const float* __restrict__ x,
                                                 const float* __restrict__ prior,
                                                 const float* __restrict__ Wlin,
                                                 const float* __restrict__ whead,
                                                 const float* __restrict__ asrc,
                                                 const float* __restrict__ adst) {
    __shared__ float xs[2][32][33];
    __shared__ float ws2[2][32][130];
    __shared__ float hpt[32][130];

    const int ib = blockIdx.x;
    const int nb = ib * 32;
    const int b = blockIdx.y;
    const int t = threadIdx.x;
    const int tr = t >> 4;
    const int tc = t & 15;

    // ---- Phase A: hp tile (8 K-chunks, double-buffered) ----
    ull acc[2][4];
#pragma unroll
    for (int ar = 0; ar < 2; ++ar)
#pragma unroll
        for (int c = 0; c < 4; ++c) acc[ar][c] = 0ull;

#pragma unroll
    for (int it = 0; it < 4; ++it) {
        int idx = t + 256 * it;
        int r = idx >> 5, k = idx & 31;
        int gn = nb + r;
        xs[0][r][k] = (gn < Nn) ? x[(b * Nn + gn) * Ii + k] : 0.f;
    }
#pragma unroll
    for (int it = 0; it < 16; ++it) {
        int idx = t + 256 * it;
        int p = idx >> 5, k = idx & 31;
        ws2[0][k][p] = Wlin[p * Ii + k];
    }
    __syncthreads();

    for (int kbi = 0; kbi < 8; ++kbi) {
        const int cur = kbi & 1;
        if (kbi < 7) {
            const int kb = (kbi + 1) * 32;
            const int nxt = 1 - cur;
#pragma unroll
            for (int it = 0; it < 4; ++it) {
                int idx = t + 256 * it;
                int r = idx >> 5, k = idx & 31;
                int gn = nb + r;
                xs[nxt][r][k] = (gn < Nn) ? x[(b * Nn + gn) * Ii + kb + k] : 0.f;
            }
#pragma unroll
            for (int it = 0; it < 16; ++it) {
                int idx = t + 256 * it;
                int p = idx >> 5, k = idx & 31;
                ws2[nxt][k][p] = Wlin[p * Ii + kb + k];
            }
        }
#pragma unroll
        for (int k = 0; k < 32; ++k) {
            ull pp0 = packf2(xs[cur][tr][k]);
            ull pp1 = packf2(xs[cur][tr + 16][k]);
#pragma unroll
            for (int c = 0; c < 4; ++c) {
                ull wv = *(const ull*)&ws2[cur][k][2 * tc + 32 * c];
                fma2(acc[0][c], pp0, wv);
                fma2(acc[1][c], pp1, wv);
            }
        }
        __syncthreads();
    }

#pragma unroll
    for (int ar = 0; ar < 2; ++ar) {
        int r = tr + 16 * ar;
        int gn = nb + r;
        bool isprior = (gn == Nn);
#pragma unroll
        for (int c = 0; c < 4; ++c) {
            int col = 2 * tc + 32 * c;
            float lo, hi;
            unpackf2(acc[ar][c], lo, hi);
            if (isprior) { lo = prior[b * Oo + col]; hi = prior[b * Oo + col + 1]; }
            hpt[r][col] = lo;
            hpt[r][col + 1] = hi;
        }
    }
    __syncthreads();
    {
        int col = t & 127;
        int half = t >> 7;
        float s = 0.f;
#pragma unroll
        for (int r = half * 16; r < half * 16 + 16; ++r) s += hpt[r][col];
        g_part[((b * 64 + ib) * 2 + half) * Oo + col] = s;
    }

    // ---- Phase B: 16 chunks (4 heads x 4 K-chunks), double-buffered ----
#pragma unroll
    for (int it = 0; it < 16; ++it) {
        int idx = t + 256 * it;
        int o = idx >> 7, p = idx & 127;
        ws2[0][o][p] = whead[(size_t)o * Oo + p];
    }
    ull a2[2][4];
#pragma unroll
    for (int ar = 0; ar < 2; ++ar)
#pragma unroll
        for (int c = 0; c < 4; ++c) a2[ar][c] = 0ull;
    __syncthreads();

    for (int ci = 0; ci < 16; ++ci) {
        const int cur = ci & 1;
        if (ci < 15) {
            const int nh = (ci + 1) >> 2;
            const int nkb = ((ci + 1) & 3) * 32;
            const int nxt = 1 - cur;
#pragma unroll
            for (int it = 0; it < 16; ++it) {
                int idx = t + 256 * it;
                int o = idx >> 7, p = idx & 127;
                ws2[nxt][o][p] = whead[(size_t)(nh * Oo + nkb + o) * Oo + p];
            }
        }
        const int kb = (ci & 3) * 32;
#pragma unroll
        for (int k = 0; k < 32; ++k) {
            ull pp0 = packf2(hpt[tr][kb + k]);
            ull pp1 = packf2(hpt[tr + 16][kb + k]);
#pragma unroll
            for (int c = 0; c < 4; ++c) {
                ull wv = *(const ull*)&ws2[cur][k][2 * tc + 32 * c];
                fma2(a2[0][c], pp0, wv);
                fma2(a2[1][c], pp1, wv);
            }
        }
        if ((ci & 3) == 3) {
            const int h = ci >> 2;
            const int bh = b * Hh + h;
#pragma unroll
            for (int ar = 0; ar < 2; ++ar) {
                int r = tr + 16 * ar;
                int gn = nb + r;
                float ps = 0.f, pd = 0.f;
#pragma unroll
                for (int c = 0; c < 4; ++c) {
                    int col = 2 * tc + 32 * c;
                    float lo, hi;
                    unpackf2(a2[ar][c], lo, hi);
                    *(float2*)&g_hph[((size_t)bh * N1 + gn) * Oo + col] = make_float2(lo, hi);
                    float t0 = fast_tanh(lo);
                    float t1 = fast_tanh(hi);
                    ps = fmaf(t0, asrc[h * Oo + col], fmaf(t1, asrc[h * Oo + col + 1], ps));
                    pd = fmaf(t0, adst[h * Oo + col], fmaf(t1, adst[h * Oo + col + 1], pd));
                }
#pragma unroll
                for (int off = 8; off; off >>= 1) {
                    ps += __shfl_xor_sync(0xffffffffu, ps, off);
                    pd += __shfl_xor_sync(0xffffffffu, pd, off);
                }
                if (tc == 0) {
                    g_ssrc[bh * N1 + gn] = ps;
                    g_sdst[bh * N1 + gn] = pd;
                }
            }
#pragma unroll
            for (int ar = 0; ar < 2; ++ar)
#pragma unroll
                for (int c = 0; c < 4; ++c) a2[ar][c] = 0ull;
        }
        __syncthreads();
    }
}

// ---------------- K2c: meanhp[b,h] = (reduce g_part -> mhp0[b]) @ w_head[h] ----------------
__global__ __launch_bounds__(128) void k2c_meanhp(const float* __restrict__ whead) {
    __shared__ float m0[Oo];
    const int h = blockIdx.x;
    const int b = blockIdx.y;
    const int t = threadIdx.x;
    float s = 0.f;
#pragma unroll 4
    for (int p = 0; p < 128; ++p) s += g_part[(b * 128 + p) * Oo + t];
    m0[t] = s * (1.f / (float)N1);
    __syncthreads();
    float acc = 0.f;
#pragma unroll 8
    for (int o = 0; o < Oo; ++o) acc = fmaf(m0[o], whead[(h * Oo + o) * Oo + t], acc);
    g_meanhp[(b * Hh + h) * Oo + t] = acc;
}

// ---------------- KSort1: mask detect + chunk max + chunk sort (composite w/ dead bit) ----
// composite = key<<16 | dead<<15 | n   (n in [0,2048) fits 11 bits)
__global__ __launch_bounds__(256) void ksort1(const void* __restrict__ xmask) {
    __shared__ ull ch[256];
    __shared__ float red8[8];
    __shared__ int sbyteflag;
    const int c = blockIdx.x;    // chunk 0..7
    const int bh = blockIdx.y;
    const int b = bh / Hh;
    const int t = threadIdx.x;

    if (t == 0) sbyteflag = 0;
    __syncthreads();
    {
        const unsigned* mw = (const unsigned*)xmask;
        bool loc = false;
#pragma unroll
        for (int n = t; n < 2048; n += 256)   // 8192 bytes, safe for both layouts
            if (mw[n] > 1u) loc = true;
        if (loc) sbyteflag = 1;   // benign same-value race
    }
    __syncthreads();
    const bool mii = (sbyteflag == 0);

    const int n = c * 256 + t;
    float sd = g_sdst[bh * N1 + n];
    bool mj = mii ? (((const int*)xmask)[b * N1 + n] != 0)
                  : (((const unsigned char*)xmask)[b * N1 + n] != 0);

    // chunk max over unmasked
    float v = mj ? -INFINITY : sd;
#pragma unroll
    for (int off = 16; off; off >>= 1) v = fmaxf(v, __shfl_xor_sync(0xffffffffu, v, off));
    if ((t & 31) == 0) red8[t >> 5] = v;
    __syncthreads();
    if (t == 0) {
        float m = red8[0];
#pragma unroll
        for (int i = 1; i < 8; ++i) m = fmaxf(m, red8[i]);
        g_cmax[bh * 8 + c] = m;
        g_mask_is_int = mii ? 1 : 0;   // every block writes the same value
    }

    ch[t] = ((ull)f2sort(sd) << 16) | (mj ? 0x8000ull : 0ull) | (unsigned)n;
    __syncthreads();
    for (int k = 2; k <= 256; k <<= 1) {
        for (int j = k >> 1; j > 0; j >>= 1) {
            int ixj = t ^ j;
            if (ixj > t) {
                bool up = ((t & k) == 0);
                ull ci = ch[t], cj = ch[ixj];
                if (up ? (ci > cj) : (ci < cj)) {
                    ch[t] = cj;
                    ch[ixj] = ci;
                }
            }
            __syncthreads();
        }
    }
    g_comps[bh * N1 + n] = ch[t];
}

// ---------------- KMerge: wide merge-by-rank + ALL factors from composites (R14 config) ----
__global__ __launch_bounds__(256) void kmerge(const void* __restrict__ xmask) {
    __shared__ ull comps[N1];      // 16 KB (8 sorted chunks of 256)
    const int c = blockIdx.x;      // own chunk 0..7
    const int bh = blockIdx.y;
    const int b = bh / Hh;
    const int t = threadIdx.x;

    for (int i = t; i < N1; i += 256) comps[i] = g_comps[bh * N1 + i];

    // Mdst from per-chunk maxima
    float Mdst = -INFINITY;
#pragma unroll
    for (int i = 0; i < 8; ++i) Mdst = fmaxf(Mdst, g_cmax[bh * 8 + i]);
    const bool nou = (Mdst == -INFINITY);
    const bool mii = (g_mask_is_int != 0);

    // natural-order factors: Ei/Fi/runi
    {
        int n = c * 256 + t;
        int gidx = bh * N1 + n;
        float si = g_ssrc[gidx];
        bool mj = mii ? (((const int*)xmask)[b * N1 + n] != 0)
                      : (((const unsigned char*)xmask)[b * N1 + n] != 0);
        bool dead = nou || mj;
        float xm = si + Mdst;
        float m = (xm >= 0.f) ? xm : SLOPEF * xm;
        g_Ei[gidx] = dead ? 0.f : __expf(xm - m);
        g_Fi[gidx] = dead ? 0.f : __expf(SLOPEF * xm - m);
        g_runi[gidx] = dead ? 1 : 0;
    }
    __syncthreads();

    // merge-by-rank (exact: composites unique) + sorted-order outputs
    {
        int slot = c * 256 + t;
        ull e = comps[slot];
        int rank = t;              // local position within own sorted chunk
#pragma unroll
        for (int c2 = 0; c2 < 8; ++c2) {
            if (c2 == c) continue;
            const int base = c2 << 8;
            int lo = 0, hi = 256;
#pragma unroll
            for (int it = 0; it < 9; ++it) {
                if (lo < hi) {
                    int mid = (lo + hi) >> 1;
                    if (comps[base + mid] < e) lo = mid + 1; else hi = mid;
                }
            }
            rank += lo;
        }
        int j = (int)(e & 0x7FFu);
        float key = sort2f((unsigned)(e >> 16));   // bit-exact s_dst[j]
        bool deadj = nou || ((e >> 15) & 1ull);
        int o = bh * N1 + rank;
        g_skey[o] = key;
        g_sidx[o] = j;
        g_wE[o] = deadj ? 0.f : __expf(key - Mdst);
        g_wF[o] = deadj ? 0.f : __expf(SLOPEF * (key - Mdst));
    }
}

// ---------------- KScan: segmented scans, 64 segments x 32 rows ----------------
__global__ __launch_bounds__(256) void kscan() {
    __shared__ float wE[SEGLEN], wF[SEGLEN];
    __shared__ int sidx[SEGLEN];
    const int s = blockIdx.x;
    const int bh = blockIdx.y;
    const int t = threadIdx.x;
    const int col = t & 127;
    const int job = t >> 7;

    if (t < SEGLEN) {
        int r = s * SEGLEN + t;
        wE[t] = g_wE[bh * N1 + r];
        wF[t] = g_wF[bh * N1 + r];
        sidx[t] = g_sidx[bh * N1 + r];
    }
    __syncthreads();

    const float* hph = g_hph + (size_t)bh * N1 * Oo;
    const size_t outbase = ((size_t)bh * NP1 + s * SEGLEN) * Oo;

    if (job == 0) {
        float acc = 0.f, sacc = 0.f;
#pragma unroll 8
        for (int r = 0; r < SEGLEN; ++r) {
            float v = hph[(size_t)sidx[r] * Oo + col];
            acc = fmaf(wF[r], v, acc);
            g_PF[outbase + (size_t)(r + 1) * Oo + col] = acc;
            if (col == 0) {
                sacc += wF[r];
                g_sPF[bh * NP1 + s * SEGLEN + r + 1] = sacc;
            }
        }
    } else {
        float acc = 0.f, sacc = 0.f;
#pragma unroll 8
        for (int r = SEGLEN - 1; r >= 0; --r) {
            float v = hph[(size_t)sidx[r] * Oo + col];
            acc = fmaf(wE[r], v, acc);
            g_SE[outbase + (size_t)r * Oo + col] = acc;
            if (col == 0) {
                sacc += wE[r];
                g_sSE[bh * NP1 + s * SEGLEN + r] = sacc;
            }
        }
    }
}

// ---------------- KTiOff: staged segment offsets + per-row threshold + 1/l ----------------
__global__ __launch_bounds__(1024) void ktioff() {
    __shared__ float keys[N1];                 // 8 KB
    __shared__ float bufE[SEGS][Oo];           // 32 KB segment-head SE rows
    __shared__ float bufF[SEGS][Oo];           // 32 KB segment-tail PF rows
    __shared__ float sheadE[SEGS], stailF[SEGS];
    __shared__ float ssoffE[SEGS + 1], ssoffF[SEGS + 1];
    const int bh = blockIdx.x;
    const int t = threadIdx.x;

    for (int i = t; i < SEGS * Oo; i += 1024) {
        int s = i >> 7, col = i & 127;
        bufE[s][col] = g_SE[((size_t)bh * NP1 + s * SEGLEN) * Oo + col];
        bufF[s][col] = g_PF[((size_t)bh * NP1 + s * SEGLEN + SEGLEN) * Oo + col];
    }
    if (t < SEGS) sheadE[t] = g_sSE[bh * NP1 + t * SEGLEN];
    else if (t < 2 * SEGS) stailF[t - SEGS] = g_sPF[bh * NP1 + (t - SEGS) * SEGLEN + SEGLEN];
    for (int i = t; i < N1; i += 1024) keys[i] = g_skey[bh * N1 + i];
    __syncthreads();

    if (t < 128) {
        float acc = 0.f;
        for (int s = SEGS - 1; s >= 0; --s) {
            g_offE[(bh * SEGS + s) * Oo + t] = acc;
            acc += bufE[s][t];
        }
        float accF = 0.f;
        for (int s = 0; s < SEGS; ++s) {
            g_offF[(bh * SEGS + s) * Oo + t] = accF;
            accF += bufF[s][t];
        }
    } else if (t == 128) {
        float a = 0.f;
        for (int s = SEGS - 1; s >= 0; --s) { ssoffE[s] = a; a += sheadE[s]; }
    } else if (t == 129) {
        float aF = 0.f;
        for (int s = 0; s < SEGS; ++s) { ssoffF[s] = aF; aF += stailF[s]; }
    }
    __syncthreads();

#pragma unroll
    for (int i = t; i < N1; i += 1024) {
        int idx = bh * N1 + i;
        float target = -g_ssrc[idx];
        int lo = 0, hi = N1;
#pragma unroll
        for (int it = 0; it < 12; ++it) {
            if (lo < hi) {
                int mid = (lo + hi) >> 1;
                if (keys[mid] >= target) hi = mid; else lo = mid + 1;
            }
        }
        int ti = lo;
        float Ei = g_Ei[idx], Fi = g_Fi[idx];
        float sse = (ti == N1) ? 0.f : g_sSE[bh * NP1 + ti] + ssoffE[ti >> SEGSH];
        float spf = (ti == 0) ? 0.f : g_sPF[bh * NP1 + ti] + ssoffF[(ti - 1) >> SEGSH];
        float li = Ei * sse + Fi * spf;
        g_ti[idx] = ti;
        g_invl[idx] = 1.f / li;
    }
}

// ---------------- KOut: gather + combine + head-mean + bias (single-barrier staging) ------
__global__ __launch_bounds__(256) void kout(const float* __restrict__ bias,
                                            float* __restrict__ out) {
    __shared__ float mhs[Hh][Oo];
    __shared__ int tis[Hh][32];
    __shared__ float Eis[Hh][32], Fis[Hh][32], invl[Hh][32];
    __shared__ unsigned char runi[Hh][32];

    const int ib = blockIdx.x;
    const int b = blockIdx.y;
    const int t = threadIdx.x;
    const int col = t & 127;
    const int rh = t >> 7;

    // stage ALL heads' row constants + meanhp once
    if (t < 128) {
        int h = t >> 5, r = t & 31;
        int idx = (b * Hh + h) * N1 + ib * 32 + r;
        tis[h][r] = g_ti[idx];
        Eis[h][r] = g_Ei[idx];
        Fis[h][r] = g_Fi[idx];
        invl[h][r] = g_invl[idx];
        runi[h][r] = g_runi[idx];
    }
    for (int i = t; i < Hh * Oo; i += 256)
        mhs[i >> 7][i & 127] = g_meanhp[b * Hh * Oo + i];
    __syncthreads();

    float sum[16];
#pragma unroll
    for (int rr = 0; rr < 16; ++rr) sum[rr] = 0.f;

    for (int h = 0; h < Hh; ++h) {
        const int bh = b * Hh + h;
#pragma unroll 4
        for (int rr = 0; rr < 16; ++rr) {
            int r = rh + 2 * rr;
            if (runi[h][r]) { sum[rr] += mhs[h][col]; continue; }
            int ti = tis[h][r];
            float se = (ti == N1) ? 0.f
                : g_SE[((size_t)bh * NP1 + ti) * Oo + col] + g_offE[(bh * SEGS + (ti >> SEGSH)) * Oo + col];
            float pf = (ti == 0) ? 0.f
                : g_PF[((size_t)bh * NP1 + ti) * Oo + col] + g_offF[(bh * SEGS + ((ti - 1) >> SEGSH)) * Oo + col];
            sum[rr] += (Eis[h][r] * se + Fis[h][r] * pf) * invl[h][r];
        }
    }

    float* outp = out + ((size_t)b * N1 + ib * 32) * Oo;
#pragma unroll
    for (int rr = 0; rr < 16; ++rr) {
        int r = rh + 2 * rr;
        outp[r * Oo + col] = 0.25f * sum[rr] + bias[col];
    }
}

// ---------------- launch ----------------
extern "C" void kernel_launch(void* const* d_in, const int* in_sizes, int n_in,
                              void* d_out, int out_size) {
    const float* x = (const float*)d_in[0];
    const float* prior = (const float*)d_in[1];
    const void* xmask = d_in[2];
    const float* Wlin = (const float*)d_in[3];
    const float* whead = (const float*)d_in[4];
    const float* asrc = (const float*)d_in[5];
    const float* adst = (const float*)d_in[6];
    const float* bias = (const float*)d_in[7];
    float* out = (float*)d_out;

    k12_fused<<<dim3(64, Bb), 256>>>(x, prior, Wlin, whead, asrc, adst);
    k2c_meanhp<<<dim3(Hh, Bb), 128>>>(whead);
    ksort1<<<dim3(8, NBH), 256>>>(xmask);
    kmerge<<<dim3(8, NBH), 256>>>(xmask);
    kscan<<<dim3(SEGS, NBH), 256>>>();
    ktioff<<<NBH, 1024>>>();
    kout<<<dim3(64, Bb), 256>>>(bias, out);
}